// round 2
// baseline (speedup 1.0000x reference)
#include <cuda_runtime.h>
#include <math.h>

#define Bc   64
#define Fc   512
#define DIN  256
#define Hc   768
#define NHc  12
#define Vc   256
#define DHc  64
#define BF   (Bc*Fc)               // 32768
#define BFH  (BF*Hc)               // 25165824

// Scratch (static __device__ arrays per allocation rules)
__device__ float g_buf1[BFH];
__device__ float g_buf2[BFH];
__device__ float g_weT[Vc*Hc];
__device__ float g_k[Vc*Hc];
__device__ float g_v[Vc*Hc];

// ---------------------------------------------------------------------------
// C[m][n] = sum_k A[m*K+k] * W[n*K+k] + bias[n]   ("NT": both K-contiguous)
// 128x128 tile, BK=8, 8x8 per thread, 256 threads. Requires M%128==0,
// N%128==0, K%8==0 (all shapes here satisfy this).
// ---------------------------------------------------------------------------
__global__ __launch_bounds__(256) void sgemm_nt(
    const float* __restrict__ A, const float* __restrict__ W,
    const float* __restrict__ bias, float* __restrict__ C,
    int M, int N, int K)
{
    __shared__ float As[8][128];
    __shared__ float Ws[8][128];
    const int bm = blockIdx.y * 128;
    const int bn = blockIdx.x * 128;
    const int tid = threadIdx.x;
    const int tx = tid & 15;
    const int ty = tid >> 4;
    const int lrow = tid >> 1;
    const int lseg = (tid & 1) * 4;

    float acc[8][8];
    #pragma unroll
    for (int i = 0; i < 8; i++)
        #pragma unroll
        for (int j = 0; j < 8; j++) acc[i][j] = 0.f;

    const float* Ap = A + (size_t)(bm + lrow) * K + lseg;
    const float* Wp = W + (size_t)(bn + lrow) * K + lseg;

    for (int kt = 0; kt < K; kt += 8) {
        float4 av = *(const float4*)(Ap + kt);
        float4 wv = *(const float4*)(Wp + kt);
        As[lseg+0][lrow] = av.x; As[lseg+1][lrow] = av.y;
        As[lseg+2][lrow] = av.z; As[lseg+3][lrow] = av.w;
        Ws[lseg+0][lrow] = wv.x; Ws[lseg+1][lrow] = wv.y;
        Ws[lseg+2][lrow] = wv.z; Ws[lseg+3][lrow] = wv.w;
        __syncthreads();
        #pragma unroll
        for (int kk = 0; kk < 8; kk++) {
            float4 a0 = *(const float4*)&As[kk][ty*8];
            float4 a1 = *(const float4*)&As[kk][ty*8+4];
            float4 w0 = *(const float4*)&Ws[kk][tx*8];
            float4 w1 = *(const float4*)&Ws[kk][tx*8+4];
            float ra[8] = {a0.x,a0.y,a0.z,a0.w,a1.x,a1.y,a1.z,a1.w};
            float rw[8] = {w0.x,w0.y,w0.z,w0.w,w1.x,w1.y,w1.z,w1.w};
            #pragma unroll
            for (int i = 0; i < 8; i++)
                #pragma unroll
                for (int j = 0; j < 8; j++)
                    acc[i][j] += ra[i] * rw[j];
        }
        __syncthreads();
    }
    float bv[8];
    #pragma unroll
    for (int j = 0; j < 8; j++) bv[j] = bias ? bias[bn + tx*8 + j] : 0.f;
    #pragma unroll
    for (int i = 0; i < 8; i++) {
        float* cp = C + (size_t)(bm + ty*8 + i) * N + bn + tx*8;
        float4 o0 = {acc[i][0]+bv[0], acc[i][1]+bv[1], acc[i][2]+bv[2], acc[i][3]+bv[3]};
        float4 o1 = {acc[i][4]+bv[4], acc[i][5]+bv[5], acc[i][6]+bv[6], acc[i][7]+bv[7]};
        *(float4*)cp       = o0;
        *(float4*)(cp + 4) = o1;
    }
}

// ---------------------------------------------------------------------------
// GCN aggregation: graph is the 5-node chain 0->1->2->3->4 on the F axis.
// deg[f] = 2 for f in {1,2,3,4}, else 1. coef(0->1)=1/sqrt(2), others 0.5.
// x_time[b,f,:] = h2[b,f,:]/deg[f] + coef * h2[b,f-1,:] (for f in 1..4) + b_gcn
// ---------------------------------------------------------------------------
__global__ void gcn_kernel(const float* __restrict__ h2,
                           const float* __restrict__ b_gcn,
                           float* __restrict__ x_time)
{
    int idx = blockIdx.x * blockDim.x + threadIdx.x;
    if (idx >= BFH) return;
    int hcol = idx % Hc;
    int f = (idx / Hc) % Fc;
    float val = h2[idx];
    float r;
    if (f >= 1 && f <= 4) {
        float coef = (f == 1) ? 0.70710678118654752440f : 0.5f;
        r = 0.5f * val + coef * h2[idx - Hc];
    } else {
        r = val;
    }
    x_time[idx] = r + b_gcn[hcol];
}

// word_embedding is (H, V) row-major; weT[v*H + h] = we[h*V + v]
__global__ void transpose_we(const float* __restrict__ we, float* __restrict__ weT)
{
    int idx = blockIdx.x * blockDim.x + threadIdx.x;
    if (idx >= Vc*Hc) return;
    int h = idx % Hc, v = idx / Hc;
    weT[idx] = we[h*Vc + v];
}

// ---------------------------------------------------------------------------
// Fused attention. grid = (B*NH, F/64), block = 512 (16 warps x 4 rows).
// k/v/q staged in smem with row stride 65 (conflict-free). K/V are
// batch-invariant (shape V x H).
// ---------------------------------------------------------------------------
#define ATTN_SMEM_FLOATS (2*Vc*65 + 64*65 + 64*256)
#define ATTN_SMEM_BYTES  (ATTN_SMEM_FLOATS * 4)

__global__ __launch_bounds__(512) void attn_kernel(
    const float* __restrict__ q, const float* __restrict__ kmat,
    const float* __restrict__ vmat, float* __restrict__ o)
{
    extern __shared__ float sm[];
    float* ks = sm;                 // [Vc][65]
    float* vs = ks + Vc*65;         // [Vc][65]
    float* qs = vs + Vc*65;         // [64][65]
    float* ps = qs + 64*65;         // [64][256]
    const int b  = blockIdx.x / NHc;
    const int h  = blockIdx.x % NHc;
    const int f0 = blockIdx.y * 64;
    const int tid  = threadIdx.x;
    const int lane = tid & 31;
    const int warp = tid >> 5;

    for (int e = tid; e < Vc*DHc; e += 512) {
        int t = e >> 6, d = e & 63;
        ks[t*65 + d] = kmat[t*Hc + h*DHc + d];
        vs[t*65 + d] = vmat[t*Hc + h*DHc + d];
    }
    for (int e = tid; e < 64*DHc; e += 512) {
        int r = e >> 6, d = e & 63;
        qs[r*65 + d] = q[(size_t)(b*Fc + f0 + r)*Hc + h*DHc + d];
    }
    __syncthreads();

    const int r0 = warp * 4;
    float acc[4][8];
    #pragma unroll
    for (int i = 0; i < 4; i++)
        #pragma unroll
        for (int j = 0; j < 8; j++) acc[i][j] = 0.f;

    #pragma unroll 4
    for (int d = 0; d < DHc; d++) {
        float q0 = qs[(r0+0)*65 + d];
        float q1 = qs[(r0+1)*65 + d];
        float q2 = qs[(r0+2)*65 + d];
        float q3 = qs[(r0+3)*65 + d];
        #pragma unroll
        for (int j = 0; j < 8; j++) {
            float kd = ks[(j*32 + lane)*65 + d];
            acc[0][j] += q0 * kd;
            acc[1][j] += q1 * kd;
            acc[2][j] += q2 * kd;
            acc[3][j] += q3 * kd;
        }
    }
    #pragma unroll
    for (int rr = 0; rr < 4; rr++) {
        float m = -1e30f;
        #pragma unroll
        for (int j = 0; j < 8; j++) { acc[rr][j] *= 0.125f; m = fmaxf(m, acc[rr][j]); }
        #pragma unroll
        for (int off = 16; off > 0; off >>= 1)
            m = fmaxf(m, __shfl_xor_sync(0xffffffffu, m, off));
        float sum = 0.f;
        #pragma unroll
        for (int j = 0; j < 8; j++) {
            float p = __expf(acc[rr][j] - m);
            acc[rr][j] = p; sum += p;
        }
        #pragma unroll
        for (int off = 16; off > 0; off >>= 1)
            sum += __shfl_xor_sync(0xffffffffu, sum, off);
        float inv = 1.f / sum;
        #pragma unroll
        for (int j = 0; j < 8; j++)
            ps[(r0+rr)*256 + j*32 + lane] = acc[rr][j] * inv;
    }
    __syncwarp();

    float o0[4] = {0,0,0,0}, o1[4] = {0,0,0,0};
    for (int t = 0; t < Vc; t++) {
        float v0 = vs[t*65 + lane];
        float v1 = vs[t*65 + lane + 32];
        #pragma unroll
        for (int rr = 0; rr < 4; rr++) {
            float pt = ps[(r0+rr)*256 + t];
            o0[rr] += pt * v0;
            o1[rr] += pt * v1;
        }
    }
    #pragma unroll
    for (int rr = 0; rr < 4; rr++) {
        float* op = o + (size_t)(b*Fc + f0 + r0 + rr)*Hc + h*DHc;
        op[lane]      = o0[rr];
        op[lane + 32] = o1[rr];
    }
}

// ---------------------------------------------------------------------------
extern "C" void kernel_launch(void* const* d_in, const int* in_sizes, int n_in,
                              void* d_out, int out_size)
{
    const float* x     = (const float*)d_in[0];
    const float* we    = (const float*)d_in[1];
    const float* W_lin = (const float*)d_in[2];
    const float* b_lin = (const float*)d_in[3];
    const float* W_gcn = (const float*)d_in[4];
    const float* b_gcn = (const float*)d_in[5];
    const float* inw   = (const float*)d_in[6];
    const float* inb   = (const float*)d_in[7];
    const float* outw  = (const float*)d_in[8];
    const float* outb  = (const float*)d_in[9];
    float* out = (float*)d_out;

    float *buf1, *buf2, *weT, *kbuf, *vbuf;
    cudaGetSymbolAddress((void**)&buf1, g_buf1);
    cudaGetSymbolAddress((void**)&buf2, g_buf2);
    cudaGetSymbolAddress((void**)&weT,  g_weT);
    cudaGetSymbolAddress((void**)&kbuf, g_k);
    cudaGetSymbolAddress((void**)&vbuf, g_v);

    // K/V projections are batch-invariant: compute once over (V, H).
    transpose_we<<<(Vc*Hc + 255)/256, 256>>>(we, weT);
    sgemm_nt<<<dim3(Hc/128, Vc/128), 256>>>(weT, inw +     (size_t)Hc*Hc, inb +     Hc, kbuf, Vc, Hc, Hc);
    sgemm_nt<<<dim3(Hc/128, Vc/128), 256>>>(weT, inw + 2*(size_t)Hc*Hc, inb + 2*Hc, vbuf, Vc, Hc, Hc);

    // h1 = x @ W_lin^T + b_lin
    sgemm_nt<<<dim3(Hc/128, BF/128), 256>>>(x, W_lin, b_lin, buf1, BF, Hc, DIN);
    // h2 = h1 @ W_gcn^T   (b_gcn applied after aggregation)
    sgemm_nt<<<dim3(Hc/128, BF/128), 256>>>(buf1, W_gcn, nullptr, buf2, BF, Hc, Hc);
    // x_time -> first half of d_out
    gcn_kernel<<<(BFH + 255)/256, 256>>>(buf2, b_gcn, out);
    // q = x_time @ Wq^T + bq
    sgemm_nt<<<dim3(Hc/128, BF/128), 256>>>(out, inw, inb, buf1, BF, Hc, Hc);
    // attention -> buf2
    cudaFuncSetAttribute(attn_kernel, cudaFuncAttributeMaxDynamicSharedMemorySize, ATTN_SMEM_BYTES);
    attn_kernel<<<dim3(Bc*NHc, Fc/64), 512, ATTN_SMEM_BYTES>>>(buf1, kbuf, vbuf, buf2);
    // x_out = o @ out_proj^T + b -> second half of d_out
    sgemm_nt<<<dim3(Hc/128, BF/128), 256>>>(buf2, outw, outb, out + BFH, BF, Hc, Hc);
}

// round 3
// speedup vs baseline: 2.1769x; 2.1769x over previous
#include <cuda_runtime.h>
#include <math.h>
#include <stdint.h>

#define Bc   64
#define Fc   512
#define DIN  256
#define Hc   768
#define NHc  12
#define Vc   256
#define DHc  64
#define BF   (Bc*Fc)               // 32768
#define BFH  (BF*Hc)               // 25165824

// Scratch (static __device__ arrays per allocation rules)
__device__ float g_buf1[BFH];
__device__ float g_buf2[BFH];
__device__ float g_weT[Vc*Hc];
__device__ float g_k[Vc*Hc];
__device__ float g_v[Vc*Hc];

// ===========================================================================
// tf32 tensor-core GEMM:  C[m][n] = sum_k A[m*K+k]*W[n*K+k] (+ bias[n])
// Tiles: 128x128xBK16, 256 threads (8 warps in 2x4), warp tile 64x32,
// mma.sync.m16n8k8.tf32. cp.async double-buffered smem, row stride PAD=20
// (conflict-free: {20*g mod 32} = {0,20,8,28,16,4,24,12}, +c in 0..3 covers
// all 32 banks exactly once).
// Requires M%128==0, N%128==0, K%16==0 (all shapes here comply).
// ===========================================================================
#define GBM 128
#define GBN 128
#define GBK 16
#define PAD 20
#define GSMEM_FLOATS (4*GBM*PAD)          // A(2 buf) + B(2 buf)
#define GSMEM_BYTES  (GSMEM_FLOATS*4)     // 40960 B

__device__ __forceinline__ unsigned smem_u32(const void* p) {
    return (unsigned)__cvta_generic_to_shared(p);
}
__device__ __forceinline__ uint32_t f2tf32(float x) {
    uint32_t r; asm("cvt.rna.tf32.f32 %0, %1;" : "=r"(r) : "f"(x)); return r;
}
__device__ __forceinline__ void cp16(unsigned s, const void* g) {
    asm volatile("cp.async.cg.shared.global [%0], [%1], 16;\n" :: "r"(s), "l"(g));
}
__device__ __forceinline__ void cp_commit() {
    asm volatile("cp.async.commit_group;\n");
}
__device__ __forceinline__ void mma_tf32(float* d, const uint32_t* a, const uint32_t* b) {
    asm volatile(
        "mma.sync.aligned.m16n8k8.row.col.f32.tf32.tf32.f32 "
        "{%0,%1,%2,%3},{%4,%5,%6,%7},{%8,%9},{%0,%1,%2,%3};"
        : "+f"(d[0]), "+f"(d[1]), "+f"(d[2]), "+f"(d[3])
        : "r"(a[0]), "r"(a[1]), "r"(a[2]), "r"(a[3]), "r"(b[0]), "r"(b[1]));
}

__global__ __launch_bounds__(256, 2) void gemm_tf32(
    const float* __restrict__ A, const float* __restrict__ W,
    const float* __restrict__ bias, float* __restrict__ C,
    int M, int N, int K)
{
    extern __shared__ float sm[];
    float* As = sm;                 // [2][128][PAD]
    float* Bs = sm + 2*GBM*PAD;     // [2][128][PAD]
    const int tid  = threadIdx.x;
    const int lane = tid & 31, warp = tid >> 5;
    const int g = lane >> 2, c = lane & 3;
    const int wm = warp >> 2, wn = warp & 3;       // 2 x 4 warp grid
    const int bm = blockIdx.y * GBM, bn = blockIdx.x * GBN;

    const int ldrow = tid >> 2;                    // 0..63
    const int ldcol = (tid & 3) * 4;               // 0,4,8,12
    const float* Ag = A + (size_t)(bm + ldrow) * K + ldcol;
    const float* Wg = W + (size_t)(bn + ldrow) * K + ldcol;
    const size_t rowskip = (size_t)64 * K;

    const unsigned sa0 = smem_u32(As + ldrow*PAD + ldcol);
    const unsigned sa1 = smem_u32(As + (ldrow+64)*PAD + ldcol);
    const unsigned sb0 = smem_u32(Bs + ldrow*PAD + ldcol);
    const unsigned sb1 = smem_u32(Bs + (ldrow+64)*PAD + ldcol);
    const unsigned bufb = GBM*PAD*4;

    float acc[4][4][4];
    #pragma unroll
    for (int mt = 0; mt < 4; mt++)
        #pragma unroll
        for (int nt = 0; nt < 4; nt++)
            #pragma unroll
            for (int i = 0; i < 4; i++) acc[mt][nt][i] = 0.f;

    const int T = K / GBK;

    auto prefetch = [&](int j, int buf) {
        const unsigned o = buf * bufb;
        cp16(sa0 + o, Ag + (size_t)j*GBK);
        cp16(sa1 + o, Ag + rowskip + (size_t)j*GBK);
        cp16(sb0 + o, Wg + (size_t)j*GBK);
        cp16(sb1 + o, Wg + rowskip + (size_t)j*GBK);
        cp_commit();
    };

    prefetch(0, 0);
    prefetch(1, 1);

    for (int kt = 0; kt < T; kt++) {
        if (kt + 1 < T) asm volatile("cp.async.wait_group 1;\n");
        else            asm volatile("cp.async.wait_group 0;\n");
        __syncthreads();

        const float* a_s = As + (kt & 1) * GBM * PAD;
        const float* b_s = Bs + (kt & 1) * GBM * PAD;
        #pragma unroll
        for (int ks = 0; ks < 2; ks++) {
            uint32_t af[4][4], bf[4][2];
            #pragma unroll
            for (int mt = 0; mt < 4; mt++) {
                const float* p = a_s + (wm*64 + mt*16 + g)*PAD + ks*8 + c;
                af[mt][0] = f2tf32(p[0]);
                af[mt][1] = f2tf32(p[8*PAD]);
                af[mt][2] = f2tf32(p[4]);
                af[mt][3] = f2tf32(p[8*PAD + 4]);
            }
            #pragma unroll
            for (int nt = 0; nt < 4; nt++) {
                const float* p = b_s + (wn*32 + nt*8 + g)*PAD + ks*8 + c;
                bf[nt][0] = f2tf32(p[0]);
                bf[nt][1] = f2tf32(p[4]);
            }
            #pragma unroll
            for (int mt = 0; mt < 4; mt++)
                #pragma unroll
                for (int nt = 0; nt < 4; nt++)
                    mma_tf32(acc[mt][nt], af[mt], bf[nt]);
        }
        __syncthreads();
        if (kt + 2 < T) prefetch(kt + 2, kt & 1);
    }

    // Epilogue
    #pragma unroll
    for (int nt = 0; nt < 4; nt++) {
        const int col = bn + wn*32 + nt*8 + 2*c;
        float b0 = 0.f, b1 = 0.f;
        if (bias) { b0 = bias[col]; b1 = bias[col + 1]; }
        #pragma unroll
        for (int mt = 0; mt < 4; mt++) {
            const int row0 = bm + wm*64 + mt*16 + g;
            float2 v0 = { acc[mt][nt][0] + b0, acc[mt][nt][1] + b1 };
            float2 v1 = { acc[mt][nt][2] + b0, acc[mt][nt][3] + b1 };
            *(float2*)&C[(size_t)row0      * N + col] = v0;
            *(float2*)&C[(size_t)(row0+8)  * N + col] = v1;
        }
    }
}

// ---------------------------------------------------------------------------
// GCN aggregation (chain 0->1->2->3->4 on F axis)
// ---------------------------------------------------------------------------
__global__ void gcn_kernel(const float* __restrict__ h2,
                           const float* __restrict__ b_gcn,
                           float* __restrict__ x_time)
{
    int idx = blockIdx.x * blockDim.x + threadIdx.x;
    if (idx >= BFH) return;
    int hcol = idx % Hc;
    int f = (idx / Hc) % Fc;
    float val = h2[idx];
    float r;
    if (f >= 1 && f <= 4) {
        float coef = (f == 1) ? 0.70710678118654752440f : 0.5f;
        r = 0.5f * val + coef * h2[idx - Hc];
    } else {
        r = val;
    }
    x_time[idx] = r + b_gcn[hcol];
}

// word_embedding is (H, V) row-major; weT[v*H + h] = we[h*V + v]
__global__ void transpose_we(const float* __restrict__ we, float* __restrict__ weT)
{
    int idx = blockIdx.x * blockDim.x + threadIdx.x;
    if (idx >= Vc*Hc) return;
    int h = idx % Hc, v = idx / Hc;
    weT[idx] = we[h*Vc + v];
}

// ---------------------------------------------------------------------------
// Fused attention (unchanged from R1 baseline; ~5% of runtime)
// ---------------------------------------------------------------------------
#define ATTN_SMEM_FLOATS (2*Vc*65 + 64*65 + 64*256)
#define ATTN_SMEM_BYTES  (ATTN_SMEM_FLOATS * 4)

__global__ __launch_bounds__(512) void attn_kernel(
    const float* __restrict__ q, const float* __restrict__ kmat,
    const float* __restrict__ vmat, float* __restrict__ o)
{
    extern __shared__ float sm[];
    float* ks = sm;                 // [Vc][65]
    float* vs = ks + Vc*65;         // [Vc][65]
    float* qs = vs + Vc*65;         // [64][65]
    float* ps = qs + 64*65;         // [64][256]
    const int b  = blockIdx.x / NHc;
    const int h  = blockIdx.x % NHc;
    const int f0 = blockIdx.y * 64;
    const int tid  = threadIdx.x;
    const int lane = tid & 31;
    const int warp = tid >> 5;

    for (int e = tid; e < Vc*DHc; e += 512) {
        int t = e >> 6, d = e & 63;
        ks[t*65 + d] = kmat[t*Hc + h*DHc + d];
        vs[t*65 + d] = vmat[t*Hc + h*DHc + d];
    }
    for (int e = tid; e < 64*DHc; e += 512) {
        int r = e >> 6, d = e & 63;
        qs[r*65 + d] = q[(size_t)(b*Fc + f0 + r)*Hc + h*DHc + d];
    }
    __syncthreads();

    const int r0 = warp * 4;
    float acc[4][8];
    #pragma unroll
    for (int i = 0; i < 4; i++)
        #pragma unroll
        for (int j = 0; j < 8; j++) acc[i][j] = 0.f;

    #pragma unroll 4
    for (int d = 0; d < DHc; d++) {
        float q0 = qs[(r0+0)*65 + d];
        float q1 = qs[(r0+1)*65 + d];
        float q2 = qs[(r0+2)*65 + d];
        float q3 = qs[(r0+3)*65 + d];
        #pragma unroll
        for (int j = 0; j < 8; j++) {
            float kd = ks[(j*32 + lane)*65 + d];
            acc[0][j] += q0 * kd;
            acc[1][j] += q1 * kd;
            acc[2][j] += q2 * kd;
            acc[3][j] += q3 * kd;
        }
    }
    #pragma unroll
    for (int rr = 0; rr < 4; rr++) {
        float m = -1e30f;
        #pragma unroll
        for (int j = 0; j < 8; j++) { acc[rr][j] *= 0.125f; m = fmaxf(m, acc[rr][j]); }
        #pragma unroll
        for (int off = 16; off > 0; off >>= 1)
            m = fmaxf(m, __shfl_xor_sync(0xffffffffu, m, off));
        float sum = 0.f;
        #pragma unroll
        for (int j = 0; j < 8; j++) {
            float p = __expf(acc[rr][j] - m);
            acc[rr][j] = p; sum += p;
        }
        #pragma unroll
        for (int off = 16; off > 0; off >>= 1)
            sum += __shfl_xor_sync(0xffffffffu, sum, off);
        float inv = 1.f / sum;
        #pragma unroll
        for (int j = 0; j < 8; j++)
            ps[(r0+rr)*256 + j*32 + lane] = acc[rr][j] * inv;
    }
    __syncwarp();

    float o0[4] = {0,0,0,0}, o1[4] = {0,0,0,0};
    for (int t = 0; t < Vc; t++) {
        float v0 = vs[t*65 + lane];
        float v1 = vs[t*65 + lane + 32];
        #pragma unroll
        for (int rr = 0; rr < 4; rr++) {
            float pt = ps[(r0+rr)*256 + t];
            o0[rr] += pt * v0;
            o1[rr] += pt * v1;
        }
    }
    #pragma unroll
    for (int rr = 0; rr < 4; rr++) {
        float* op = o + (size_t)(b*Fc + f0 + r0 + rr)*Hc + h*DHc;
        op[lane]      = o0[rr];
        op[lane + 32] = o1[rr];
    }
}

// ---------------------------------------------------------------------------
extern "C" void kernel_launch(void* const* d_in, const int* in_sizes, int n_in,
                              void* d_out, int out_size)
{
    const float* x     = (const float*)d_in[0];
    const float* we    = (const float*)d_in[1];
    const float* W_lin = (const float*)d_in[2];
    const float* b_lin = (const float*)d_in[3];
    const float* W_gcn = (const float*)d_in[4];
    const float* b_gcn = (const float*)d_in[5];
    const float* inw   = (const float*)d_in[6];
    const float* inb   = (const float*)d_in[7];
    const float* outw  = (const float*)d_in[8];
    const float* outb  = (const float*)d_in[9];
    float* out = (float*)d_out;

    float *buf1, *buf2, *weT, *kbuf, *vbuf;
    cudaGetSymbolAddress((void**)&buf1, g_buf1);
    cudaGetSymbolAddress((void**)&buf2, g_buf2);
    cudaGetSymbolAddress((void**)&weT,  g_weT);
    cudaGetSymbolAddress((void**)&kbuf, g_k);
    cudaGetSymbolAddress((void**)&vbuf, g_v);

    // K/V projections are batch-invariant: compute once over (V, H).
    transpose_we<<<(Vc*Hc + 255)/256, 256>>>(we, weT);
    gemm_tf32<<<dim3(Hc/128, Vc/128), 256, GSMEM_BYTES>>>(weT, inw + (size_t)Hc*Hc,   inb + Hc,   kbuf, Vc, Hc, Hc);
    gemm_tf32<<<dim3(Hc/128, Vc/128), 256, GSMEM_BYTES>>>(weT, inw + 2*(size_t)Hc*Hc, inb + 2*Hc, vbuf, Vc, Hc, Hc);

    // h1 = x @ W_lin^T + b_lin
    gemm_tf32<<<dim3(Hc/128, BF/128), 256, GSMEM_BYTES>>>(x, W_lin, b_lin, buf1, BF, Hc, DIN);
    // h2 = h1 @ W_gcn^T   (b_gcn applied after aggregation)
    gemm_tf32<<<dim3(Hc/128, BF/128), 256, GSMEM_BYTES>>>(buf1, W_gcn, nullptr, buf2, BF, Hc, Hc);
    // x_time -> first half of d_out
    gcn_kernel<<<(BFH + 255)/256, 256>>>(buf2, b_gcn, out);
    // q = x_time @ Wq^T + bq
    gemm_tf32<<<dim3(Hc/128, BF/128), 256, GSMEM_BYTES>>>(out, inw, inb, buf1, BF, Hc, Hc);
    // attention -> buf2
    cudaFuncSetAttribute(attn_kernel, cudaFuncAttributeMaxDynamicSharedMemorySize, ATTN_SMEM_BYTES);
    attn_kernel<<<dim3(Bc*NHc, Fc/64), 512, ATTN_SMEM_BYTES>>>(buf1, kbuf, vbuf, buf2);
    // x_out = o @ out_proj^T + b -> second half of d_out
    gemm_tf32<<<dim3(Hc/128, BF/128), 256, GSMEM_BYTES>>>(buf2, outw, outb, out + BFH, BF, Hc, Hc);
}